// round 14
// baseline (speedup 1.0000x reference)
#include <cuda_runtime.h>
#include <cuda_bf16.h>
#include <cstdint>

typedef __nv_bfloat16 bf16;

// ---------------------------------------------------------------------------
// ChebNet GCN forward, n=4096.  (sm_100 mma.sync path; issue-bound per R12 ncu)
// Split bf16 (hi/lo), 3 cross terms, fp32 accum. M always 4096.
// bgemm_ep<NB>: 128xNBx32 tiles (NB=32/64/128 by N), cp.async 2-stage, ldmatrix.
// bgemm_wide:   256x128x32 tiles, 64x64 warp tiles (higher MMA issue fraction)
//               for the N=1120 cheb GEMMs.
// ---------------------------------------------------------------------------

#define NN 4096

__device__ float g_As [(size_t)NN * NN];
__device__ bf16  g_AsHi[(size_t)NN * NN];
__device__ bf16  g_AsLo[(size_t)NN * NN];
__device__ float g_dinv[NN];
__device__ float g_Tw1[(size_t)NN * 42];
__device__ bf16  g_TAhi[(size_t)NN * 5600 + 256];
__device__ bf16  g_TAlo[(size_t)NN * 5600 + 256];
__device__ bf16  g_TBhi[(size_t)NN * 2240 + 256];
__device__ bf16  g_TBlo[(size_t)NN * 2240 + 256];
__device__ bf16  g_W2hi[5 * 1120 * 560 + 256], g_W2lo[5 * 1120 * 560 + 256];
__device__ bf16  g_W3hi[4 * 560 * 280 + 256],  g_W3lo[4 * 560 * 280 + 256];
__device__ bf16  g_W4hi[3 * 280 * 144 + 256],  g_W4lo[3 * 280 * 144 + 256];
__device__ float g_H4 [(size_t)NN * 140];
__device__ float g_Hfc[(size_t)NN * 140];

__device__ __forceinline__ void split_bf16(float r, bf16& hi, bf16& lo) {
    hi = __float2bfloat16_rn(r);
    lo = __float2bfloat16_rn(r - __bfloat162float(hi));
}

__device__ __forceinline__ uint32_t smem_u32(const void* p) {
    uint32_t a;
    asm("{ .reg .u64 t; cvta.to.shared.u64 t, %1; cvt.u32.u64 %0, t; }" : "=r"(a) : "l"(p));
    return a;
}
__device__ __forceinline__ void cpa16(uint32_t d, const void* s) {
    asm volatile("cp.async.cg.shared.global [%0], [%1], 16;" :: "r"(d), "l"(s));
}
#define CPA_COMMIT() asm volatile("cp.async.commit_group;" ::: "memory")
#define CPA_WAIT1()  asm volatile("cp.async.wait_group 1;" ::: "memory")
#define CPA_WAIT0()  asm volatile("cp.async.wait_group 0;" ::: "memory")
#define LDSM4(r0, r1, r2, r3, a)                                              \
    asm volatile("ldmatrix.sync.aligned.m8n8.x4.shared.b16 {%0,%1,%2,%3}, [%4];" \
                 : "=r"(r0), "=r"(r1), "=r"(r2), "=r"(r3) : "r"(a))
#define LDSM4T(r0, r1, r2, r3, a)                                             \
    asm volatile("ldmatrix.sync.aligned.m8n8.x4.trans.shared.b16 {%0,%1,%2,%3}, [%4];" \
                 : "=r"(r0), "=r"(r1), "=r"(r2), "=r"(r3) : "r"(a))
#define MMA16816(d, a0, a1, a2, a3, b0, b1)                                   \
    asm volatile(                                                              \
        "mma.sync.aligned.m16n8k16.row.col.f32.bf16.bf16.f32 "                 \
        "{%0,%1,%2,%3}, {%4,%5,%6,%7}, {%8,%9}, {%0,%1,%2,%3};"                \
        : "+f"(d[0]), "+f"(d[1]), "+f"(d[2]), "+f"(d[3])                       \
        : "r"(a0), "r"(a1), "r"(a2), "r"(a3), "r"(b0), "r"(b1))

// ------------------------------ small kernels ------------------------------

__global__ void deg_kernel(const float* __restrict__ adj, float* __restrict__ dinv) {
    int r = blockIdx.x;
    const float* row = adj + (size_t)r * NN;
    float s = 0.f;
    for (int c = threadIdx.x; c < NN; c += blockDim.x) s += row[c];
    __shared__ float sh[256];
    sh[threadIdx.x] = s;
    __syncthreads();
    for (int o = 128; o > 0; o >>= 1) {
        if (threadIdx.x < o) sh[threadIdx.x] += sh[threadIdx.x + o];
        __syncthreads();
    }
    if (threadIdx.x == 0) dinv[r] = rsqrtf(fmaxf(sh[0], 1e-12f));
}

__global__ void scale_adj_split(const float* __restrict__ adj,
                                const float* __restrict__ dinv,
                                float* __restrict__ As,
                                bf16* __restrict__ hi, bf16* __restrict__ lo) {
    int r = blockIdx.x;
    float dr = dinv[r];
    size_t base = (size_t)r * NN;
    for (int c = threadIdx.x; c < NN; c += blockDim.x) {
        float v = adj[base + c] * dr * dinv[c];
        As[base + c] = v;
        bf16 h, l;
        split_bf16(v, h, l);
        hi[base + c] = h;
        lo[base + c] = l;
    }
}

__global__ void split_kernel(const float* __restrict__ src,
                             bf16* __restrict__ hi, bf16* __restrict__ lo, int n) {
    for (int i = blockIdx.x * blockDim.x + threadIdx.x; i < n;
         i += gridDim.x * blockDim.x) {
        bf16 h, l;
        split_bf16(src[i], h, l);
        hi[i] = h;
        lo[i] = l;
    }
}

__global__ void split_pad_kernel(const float* __restrict__ W,
                                 bf16* __restrict__ hi, bf16* __restrict__ lo,
                                 int rows, int cout, int ldp) {
    int tot = rows * ldp;
    for (int i = blockIdx.x * blockDim.x + threadIdx.x; i < tot;
         i += gridDim.x * blockDim.x) {
        int co = i % ldp, r = i / ldp;
        float v = (co < cout) ? W[(size_t)r * cout + co] : 0.f;
        bf16 h, l;
        split_bf16(v, h, l);
        hi[i] = h;
        lo[i] = l;
    }
}

__global__ void copy_x_kernel(const float* __restrict__ x, float* __restrict__ Tw1) {
    int i = blockIdx.x * blockDim.x + threadIdx.x;
    if (i < NN * 7) Tw1[(size_t)(i / 7) * 42 + (i % 7)] = x[i];
}

// ------------------- skinny fp32 GEMM (layer-1 cheb, FC2) -------------------
#define SKN 8
__global__ __launch_bounds__(256)
void gemm_skinny(int N, int K,
                 const float* __restrict__ A, int lda,
                 const float* __restrict__ B, int ldb,
                 float* __restrict__ C, int ldc,
                 const float* __restrict__ U, const float* __restrict__ V,
                 const float* __restrict__ bias,
                 float alpha, float beta, float gamma) {
    const int row = blockIdx.x, tid = threadIdx.x;
    const float* Arow = A + (size_t)row * lda;
    float acc[SKN];
#pragma unroll
    for (int j = 0; j < SKN; j++) acc[j] = 0.f;
    for (int k = tid; k < K; k += 256) {
        float a = Arow[k];
        const float* Bk = B + (size_t)k * ldb;
#pragma unroll
        for (int j = 0; j < SKN; j++)
            if (j < N) acc[j] += a * Bk[j];
    }
#pragma unroll
    for (int j = 0; j < SKN; j++)
#pragma unroll
        for (int o = 16; o > 0; o >>= 1)
            acc[j] += __shfl_xor_sync(0xFFFFFFFFu, acc[j], o);
    __shared__ float red[8][SKN];
    int wid = tid >> 5, lane = tid & 31;
    if (lane == 0)
#pragma unroll
        for (int j = 0; j < SKN; j++) red[wid][j] = acc[j];
    __syncthreads();
    if (tid < N) {
        float s = 0.f;
#pragma unroll
        for (int w = 0; w < 8; w++) s += red[w][tid];
        size_t idx = (size_t)row * ldc + tid;
        float r = alpha * s;
        if (U) r += beta * U[idx];
        if (V) r += gamma * V[idx];
        if (bias) r += bias[tid];
        C[idx] = r;
    }
}

// ----------------------- fp32 SIMT GEMM (layer-1 weight, FC1) ---------------
__global__ __launch_bounds__(256)
void sgemm_ep(int M, int N, int K,
              const float* __restrict__ A, int lda,
              const float* __restrict__ B, int ldb,
              float* __restrict__ C, int ldc,
              const float* __restrict__ bias, int relu,
              bf16* __restrict__ Ohi, bf16* __restrict__ Olo, int ldo) {
    __shared__ float As_s[8][132];
    __shared__ float Bs_s[8][132];
    const int tid = threadIdx.x, tx = tid % 16, ty = tid / 16;
    const int row0 = blockIdx.y * 128, col0 = blockIdx.x * 128;
    float acc[8][8];
#pragma unroll
    for (int i = 0; i < 8; i++)
#pragma unroll
        for (int j = 0; j < 8; j++) acc[i][j] = 0.f;
    const int lane32 = tid % 32, bkk = tid / 32;
    for (int k0 = 0; k0 < K; k0 += 8) {
#pragma unroll
        for (int j = 0; j < 4; j++) {
            int e = tid + 256 * j, ar = e >> 3, ak = e & 7;
            int m = row0 + ar, k = k0 + ak;
            As_s[ak][ar] = (m < M && k < K) ? A[(size_t)m * lda + k] : 0.f;
        }
#pragma unroll
        for (int j = 0; j < 4; j++) {
            int n = col0 + lane32 + 32 * j, k = k0 + bkk;
            Bs_s[bkk][lane32 + 32 * j] = (k < K && n < N) ? B[(size_t)k * ldb + n] : 0.f;
        }
        __syncthreads();
#pragma unroll
        for (int kk = 0; kk < 8; kk++) {
            float af[8], bf[8];
#pragma unroll
            for (int i = 0; i < 8; i++) af[i] = As_s[kk][ty * 8 + i];
#pragma unroll
            for (int j = 0; j < 8; j++) bf[j] = Bs_s[kk][tx * 8 + j];
#pragma unroll
            for (int i = 0; i < 8; i++)
#pragma unroll
                for (int j = 0; j < 8; j++) acc[i][j] += af[i] * bf[j];
        }
        __syncthreads();
    }
#pragma unroll
    for (int i = 0; i < 8; i++) {
        int m = row0 + ty * 8 + i;
        if (m >= M) continue;
#pragma unroll
        for (int j = 0; j < 8; j++) {
            int n = col0 + tx * 8 + j;
            if (n >= N) continue;
            float r = acc[i][j];
            if (bias) r += bias[n];
            if (relu) r = fmaxf(r, 0.f);
            if (C) C[(size_t)m * ldc + n] = r;
            if (Ohi) {
                bf16 h, l;
                split_bf16(r, h, l);
                Ohi[(size_t)m * ldo + n] = h;
                Olo[(size_t)m * ldo + n] = l;
            }
        }
    }
}

// --------------------- bf16 split mma GEMM, 128xNB tiles --------------------

template <int NB>
__global__ __launch_bounds__(256, 2)
void bgemm_ep(int N, int K,
              const bf16* __restrict__ Ahi, const bf16* __restrict__ Alo, long lda,
              const bf16* __restrict__ Bhi, const bf16* __restrict__ Blo, long ldb,
              const bf16* __restrict__ Uhi, const bf16* __restrict__ Ulo,
              const bf16* __restrict__ Vhi, const bf16* __restrict__ Vlo, long ldu,
              float alpha, float beta, float gamma,
              const float* __restrict__ bias, int relu,
              bf16* __restrict__ Ohi, bf16* __restrict__ Olo, long ldo,
              float* __restrict__ Cf, long ldc) {
    constexpr int BROW = NB + 8;
    constexpr int BPL = 32 * BROW * 2;
    constexpr int STG = 20480 + 2 * BPL;
    constexpr int BSEGS = 32 * (NB / 8);       // B segs per plane
    extern __shared__ char smem[];
    const uint32_t sb = smem_u32(smem);
    const int tid = threadIdx.x, lane = tid & 31, wid = tid >> 5;
    const int wr = wid & 3, wc = wid >> 2;
    const int g = lane >> 2, t4 = lane & 3;
    const int t8 = lane & 7, quad = lane >> 3;
    const int row0 = blockIdx.y * 128, col0 = blockIdx.x * NB;
    const int NC = (K + 31) >> 5;

    float acc[2][NB / 16][4];
#pragma unroll
    for (int i = 0; i < 2; i++)
#pragma unroll
        for (int j = 0; j < NB / 16; j++)
#pragma unroll
            for (int e = 0; e < 4; e++) acc[i][j][e] = 0.f;

    auto load_stage = [&](int st, int c) {
        const long k0 = (long)c << 5;
        char* base = smem + st * STG;
#pragma unroll
        for (int q = 0; q < 2; q++) {
            int seg = tid * 2 + q;
            int row = seg >> 2, k8 = (seg & 3) << 3;
            char* da = base + 2 * (row * 40 + k8);
            if (k0 + k8 < K) {
                cpa16(smem_u32(da), Ahi + (size_t)(row0 + row) * lda + k0 + k8);
                cpa16(smem_u32(da + 10240), Alo + (size_t)(row0 + row) * lda + k0 + k8);
            } else {
                *(uint4*)da = make_uint4(0u, 0u, 0u, 0u);
                *(uint4*)(da + 10240) = make_uint4(0u, 0u, 0u, 0u);
            }
        }
        // B loader: generic over NB (NB=32: 128 segs -> threads < 128)
#pragma unroll
        for (int q = 0; q < (BSEGS + 255) / 256; q++) {
            int seg = tid + q * 256;
            if (seg < BSEGS) {
                int row = seg / (NB / 8), n8 = (seg % (NB / 8)) << 3;
                char* db = base + 20480 + 2 * (row * BROW + n8);
                if (k0 + row < K) {
                    cpa16(smem_u32(db), Bhi + (size_t)(k0 + row) * ldb + col0 + n8);
                    cpa16(smem_u32(db + BPL), Blo + (size_t)(k0 + row) * ldb + col0 + n8);
                } else {
                    *(uint4*)db = make_uint4(0u, 0u, 0u, 0u);
                    *(uint4*)(db + BPL) = make_uint4(0u, 0u, 0u, 0u);
                }
            }
        }
    };

    load_stage(0, 0);
    CPA_COMMIT();
    if (NC > 1) load_stage(1, 1);
    CPA_COMMIT();

    const int arow = wr * 32 + ((quad & 1) << 3) + t8;
    const int acol = (quad & 2) << 2;
    const int brow = ((quad & 1) << 3) + t8;
    const int bcol = wc * (NB / 2) + ((quad & 2) << 2);

    for (int c = 0; c < NC; c++) {
        if (c < NC - 1) CPA_WAIT1(); else CPA_WAIT0();
        __syncthreads();
        const uint32_t s0 = sb + (uint32_t)((c & 1) * STG);
        const uint32_t aB = s0, bB = s0 + 20480;
#pragma unroll
        for (int kh = 0; kh < 2; kh++) {
            uint32_t ah[2][4], al[2][4];
#pragma unroll
            for (int mi = 0; mi < 2; mi++) {
                uint32_t adr = aB + 2 * ((arow + mi * 16) * 40 + acol + kh * 16);
                LDSM4(ah[mi][0], ah[mi][1], ah[mi][2], ah[mi][3], adr);
                LDSM4(al[mi][0], al[mi][1], al[mi][2], al[mi][3], adr + 10240);
            }
#pragma unroll
            for (int p = 0; p < NB / 32; p++) {
                uint32_t bh[4], bl[4];
                uint32_t bdr = bB + 2 * ((brow + kh * 16) * BROW + bcol + p * 16);
                LDSM4T(bh[0], bh[1], bh[2], bh[3], bdr);
                LDSM4T(bl[0], bl[1], bl[2], bl[3], bdr + BPL);
#pragma unroll
                for (int mi = 0; mi < 2; mi++) {
                    MMA16816(acc[mi][2 * p], ah[mi][0], ah[mi][1], ah[mi][2], ah[mi][3], bh[0], bh[1]);
                    MMA16816(acc[mi][2 * p], ah[mi][0], ah[mi][1], ah[mi][2], ah[mi][3], bl[0], bl[1]);
                    MMA16816(acc[mi][2 * p], al[mi][0], al[mi][1], al[mi][2], al[mi][3], bh[0], bh[1]);
                    MMA16816(acc[mi][2 * p + 1], ah[mi][0], ah[mi][1], ah[mi][2], ah[mi][3], bh[2], bh[3]);
                    MMA16816(acc[mi][2 * p + 1], ah[mi][0], ah[mi][1], ah[mi][2], ah[mi][3], bl[2], bl[3]);
                    MMA16816(acc[mi][2 * p + 1], al[mi][0], al[mi][1], al[mi][2], al[mi][3], bh[2], bh[3]);
                }
            }
        }
        __syncthreads();
        if (c + 2 < NC) { load_stage(c & 1, c + 2); CPA_COMMIT(); }
    }

#pragma unroll
    for (int mi = 0; mi < 2; mi++) {
        int rb = row0 + wr * 32 + mi * 16 + g;
#pragma unroll
        for (int ni = 0; ni < NB / 16; ni++) {
            int cb = col0 + wc * (NB / 2) + ni * 8 + 2 * t4;
#pragma unroll
            for (int e = 0; e < 4; e++) {
                int rr = rb + ((e >> 1) << 3);
                int cc = cb + (e & 1);
                if (cc >= N) continue;
                float r = alpha * acc[mi][ni][e];
                size_t iu = (size_t)rr * ldu + cc;
                if (Uhi) r += beta * (__bfloat162float(Uhi[iu]) + __bfloat162float(Ulo[iu]));
                if (Vhi) r += gamma * (__bfloat162float(Vhi[iu]) + __bfloat162float(Vlo[iu]));
                if (bias) r += bias[cc];
                if (relu) r = fmaxf(r, 0.f);
                if (Cf) Cf[(size_t)rr * ldc + cc] = r;
                if (Ohi) {
                    bf16 h, l;
                    split_bf16(r, h, l);
                    Ohi[(size_t)rr * ldo + cc] = h;
                    Olo[(size_t)rr * ldo + cc] = l;
                }
            }
        }
    }
}

// --------------- bf16 split mma GEMM, 256x128 tile, 64x64 warp --------------
// Higher MMA issue fraction (192 MMA : ~62 other) for big-N GEMMs.
// Stage: A 256x40x2B x2 planes = 40960 ; B 32x136x2B x2 = 17408 ; STG 58368.

#define WSTG 58368

__global__ __launch_bounds__(256, 1)
void bgemm_wide(int N, int K,
                const bf16* __restrict__ Ahi, const bf16* __restrict__ Alo, long lda,
                const bf16* __restrict__ Bhi, const bf16* __restrict__ Blo, long ldb,
                const bf16* __restrict__ Uhi, const bf16* __restrict__ Ulo,
                const bf16* __restrict__ Vhi, const bf16* __restrict__ Vlo, long ldu,
                float alpha, float beta, float gamma,
                const float* __restrict__ bias, int relu,
                bf16* __restrict__ Ohi, bf16* __restrict__ Olo, long ldo,
                float* __restrict__ Cf, long ldc) {
    extern __shared__ char smem[];
    const uint32_t sb = smem_u32(smem);
    const int tid = threadIdx.x, lane = tid & 31, wid = tid >> 5;
    const int wr = wid & 3, wc = wid >> 2;          // 4 x 2 warp grid
    const int g = lane >> 2, t4 = lane & 3;
    const int t8 = lane & 7, quad = lane >> 3;
    const int row0 = blockIdx.y * 256, col0 = blockIdx.x * 128;
    const int NC = (K + 31) >> 5;

    float acc[4][8][4];
#pragma unroll
    for (int i = 0; i < 4; i++)
#pragma unroll
        for (int j = 0; j < 8; j++)
#pragma unroll
            for (int e = 0; e < 4; e++) acc[i][j][e] = 0.f;

    auto load_stage = [&](int st, int c) {
        const long k0 = (long)c << 5;
        char* base = smem + st * WSTG;
#pragma unroll
        for (int q = 0; q < 4; q++) {
            int k8 = q << 3;
            char* da = base + 2 * (tid * 40 + k8);
            if (k0 + k8 < K) {
                cpa16(smem_u32(da), Ahi + (size_t)(row0 + tid) * lda + k0 + k8);
                cpa16(smem_u32(da + 20480), Alo + (size_t)(row0 + tid) * lda + k0 + k8);
            } else {
                *(uint4*)da = make_uint4(0u, 0u, 0u, 0u);
                *(uint4*)(da + 20480) = make_uint4(0u, 0u, 0u, 0u);
            }
        }
#pragma unroll
        for (int q = 0; q < 2; q++) {
            int seg = tid * 2 + q;
            int row = seg >> 4, n8 = (seg & 15) << 3;
            char* db = base + 40960 + 2 * (row * 136 + n8);
            if (k0 + row < K) {
                cpa16(smem_u32(db), Bhi + (size_t)(k0 + row) * ldb + col0 + n8);
                cpa16(smem_u32(db + 8704), Blo + (size_t)(k0 + row) * ldb + col0 + n8);
            } else {
                *(uint4*)db = make_uint4(0u, 0u, 0u, 0u);
                *(uint4*)(db + 8704) = make_uint4(0u, 0u, 0u, 0u);
            }
        }
    };

    load_stage(0, 0);
    CPA_COMMIT();
    if (NC > 1) load_stage(1, 1);
    CPA_COMMIT();

    const int arow = wr * 64 + ((quad & 1) << 3) + t8;
    const int acol = (quad & 2) << 2;
    const int brow = ((quad & 1) << 3) + t8;
    const int bcol = wc * 64 + ((quad & 2) << 2);

    for (int c = 0; c < NC; c++) {
        if (c < NC - 1) CPA_WAIT1(); else CPA_WAIT0();
        __syncthreads();
        const uint32_t s0 = sb + (uint32_t)((c & 1) * WSTG);
        const uint32_t aB = s0, bB = s0 + 40960;
#pragma unroll
        for (int kh = 0; kh < 2; kh++) {
            uint32_t ah[4][4], al[4][4];
#pragma unroll
            for (int mi = 0; mi < 4; mi++) {
                uint32_t adr = aB + 2 * ((arow + mi * 16) * 40 + acol + kh * 16);
                LDSM4(ah[mi][0], ah[mi][1], ah[mi][2], ah[mi][3], adr);
                LDSM4(al[mi][0], al[mi][1], al[mi][2], al[mi][3], adr + 20480);
            }
#pragma unroll
            for (int p = 0; p < 4; p++) {
                uint32_t bh[4], bl[4];
                uint32_t bdr = bB + 2 * ((brow + kh * 16) * 136 + bcol + p * 16);
                LDSM4T(bh[0], bh[1], bh[2], bh[3], bdr);
                LDSM4T(bl[0], bl[1], bl[2], bl[3], bdr + 8704);
#pragma unroll
                for (int mi = 0; mi < 4; mi++) {
                    MMA16816(acc[mi][2 * p], ah[mi][0], ah[mi][1], ah[mi][2], ah[mi][3], bh[0], bh[1]);
                    MMA16816(acc[mi][2 * p], ah[mi][0], ah[mi][1], ah[mi][2], ah[mi][3], bl[0], bl[1]);
                    MMA16816(acc[mi][2 * p], al[mi][0], al[mi][1], al[mi][2], al[mi][3], bh[0], bh[1]);
                    MMA16816(acc[mi][2 * p + 1], ah[mi][0], ah[mi][1], ah[mi][2], ah[mi][3], bh[2], bh[3]);
                    MMA16816(acc[mi][2 * p + 1], ah[mi][0], ah[mi][1], ah[mi][2], ah[mi][3], bl[2], bl[3]);
                    MMA16816(acc[mi][2 * p + 1], al[mi][0], al[mi][1], al[mi][2], al[mi][3], bh[2], bh[3]);
                }
            }
        }
        __syncthreads();
        if (c + 2 < NC) { load_stage(c & 1, c + 2); CPA_COMMIT(); }
    }

#pragma unroll
    for (int mi = 0; mi < 4; mi++) {
        int rb = row0 + wr * 64 + mi * 16 + g;
#pragma unroll
        for (int ni = 0; ni < 8; ni++) {
            int cb = col0 + wc * 64 + ni * 8 + 2 * t4;
#pragma unroll
            for (int e = 0; e < 4; e++) {
                int rr = rb + ((e >> 1) << 3);
                int cc = cb + (e & 1);
                if (cc >= N) continue;
                float r = alpha * acc[mi][ni][e];
                size_t iu = (size_t)rr * ldu + cc;
                if (Uhi) r += beta * (__bfloat162float(Uhi[iu]) + __bfloat162float(Ulo[iu]));
                if (Vhi) r += gamma * (__bfloat162float(Vhi[iu]) + __bfloat162float(Vlo[iu]));
                if (bias) r += bias[cc];
                if (relu) r = fmaxf(r, 0.f);
                if (Cf) Cf[(size_t)rr * ldc + cc] = r;
                if (Ohi) {
                    bf16 h, l;
                    split_bf16(r, h, l);
                    Ohi[(size_t)rr * ldo + cc] = h;
                    Olo[(size_t)rr * ldo + cc] = l;
                }
            }
        }
    }
}

// ------------------------------- host side ----------------------------------

#define STG128 37888
#define STG64  29696
#define STG32  25600

static void set_attrs_once() {
    static int done = 0;
    if (!done) {
        cudaFuncSetAttribute(bgemm_ep<128>, cudaFuncAttributeMaxDynamicSharedMemorySize, 2 * STG128);
        cudaFuncSetAttribute(bgemm_ep<64>, cudaFuncAttributeMaxDynamicSharedMemorySize, 2 * STG64);
        cudaFuncSetAttribute(bgemm_ep<32>, cudaFuncAttributeMaxDynamicSharedMemorySize, 2 * STG32);
        cudaFuncSetAttribute(bgemm_wide, cudaFuncAttributeMaxDynamicSharedMemorySize, 2 * WSTG);
        done = 1;
    }
}

static inline void bgemm_launch(int N, int K,
                                const bf16* Ahi, const bf16* Alo, long lda,
                                const bf16* Bhi, const bf16* Blo, long ldb,
                                const bf16* Uhi, const bf16* Ulo,
                                const bf16* Vhi, const bf16* Vlo, long ldu,
                                float al, float be, float ga,
                                const float* bias, int relu,
                                bf16* Ohi, bf16* Olo, long ldo,
                                float* Cf, long ldc) {
    set_attrs_once();
    if (N >= 1024) {
        dim3 grid((N + 127) / 128, 16);
        bgemm_wide<<<grid, 256, 2 * WSTG>>>(N, K, Ahi, Alo, lda, Bhi, Blo, ldb,
                                            Uhi, Ulo, Vhi, Vlo, ldu, al, be, ga,
                                            bias, relu, Ohi, Olo, ldo, Cf, ldc);
    } else if (N <= 280) {
        dim3 grid((N + 31) / 32, 32);
        bgemm_ep<32><<<grid, 256, 2 * STG32>>>(N, K, Ahi, Alo, lda, Bhi, Blo, ldb,
                                               Uhi, Ulo, Vhi, Vlo, ldu, al, be, ga,
                                               bias, relu, Ohi, Olo, ldo, Cf, ldc);
    } else if (N <= 560) {
        dim3 grid((N + 63) / 64, 32);
        bgemm_ep<64><<<grid, 256, 2 * STG64>>>(N, K, Ahi, Alo, lda, Bhi, Blo, ldb,
                                               Uhi, Ulo, Vhi, Vlo, ldu, al, be, ga,
                                               bias, relu, Ohi, Olo, ldo, Cf, ldc);
    } else {
        dim3 grid((N + 127) / 128, 32);
        bgemm_ep<128><<<grid, 256, 2 * STG128>>>(N, K, Ahi, Alo, lda, Bhi, Blo, ldb,
                                                 Uhi, Ulo, Vhi, Vlo, ldu, al, be, ga,
                                                 bias, relu, Ohi, Olo, ldo, Cf, ldc);
    }
}

extern "C" void kernel_launch(void* const* d_in, const int* in_sizes, int n_in,
                              void* d_out, int out_size) {
    const float* x     = (const float*)d_in[0];
    const float* adj   = (const float*)d_in[1];
    const float* W1    = (const float*)d_in[2];
    const float* b1    = (const float*)d_in[3];
    const float* W2    = (const float*)d_in[4];
    const float* b2    = (const float*)d_in[5];
    const float* W3    = (const float*)d_in[6];
    const float* b3    = (const float*)d_in[7];
    const float* W4    = (const float*)d_in[8];
    const float* b4    = (const float*)d_in[9];
    const float* fc1_w = (const float*)d_in[10];
    const float* fc1_b = (const float*)d_in[11];
    const float* fc2_w = (const float*)d_in[12];
    const float* fc2_b = (const float*)d_in[13];
    float* out = (float*)d_out;

    void* p;
    float *As, *dinv, *Tw1, *H4, *Hfc;
    bf16 *Ashi, *Aslo, *TAhi, *TAlo, *TBhi, *TBlo;
    bf16 *W2hi, *W2lo, *W3hi, *W3lo, *W4hi, *W4lo;
    cudaGetSymbolAddress(&p, g_As);   As   = (float*)p;
    cudaGetSymbolAddress(&p, g_AsHi); Ashi = (bf16*)p;
    cudaGetSymbolAddress(&p, g_AsLo); Aslo = (bf16*)p;
    cudaGetSymbolAddress(&p, g_dinv); dinv = (float*)p;
    cudaGetSymbolAddress(&p, g_Tw1);  Tw1  = (float*)p;
    cudaGetSymbolAddress(&p, g_TAhi); TAhi = (bf16*)p;
    cudaGetSymbolAddress(&p, g_TAlo); TAlo = (bf16*)p;
    cudaGetSymbolAddress(&p, g_TBhi); TBhi = (bf16*)p;
    cudaGetSymbolAddress(&p, g_TBlo); TBlo = (bf16*)p;
    cudaGetSymbolAddress(&p, g_W2hi); W2hi = (bf16*)p;
    cudaGetSymbolAddress(&p, g_W2lo); W2lo = (bf16*)p;
    cudaGetSymbolAddress(&p, g_W3hi); W3hi = (bf16*)p;
    cudaGetSymbolAddress(&p, g_W3lo); W3lo = (bf16*)p;
    cudaGetSymbolAddress(&p, g_W4hi); W4hi = (bf16*)p;
    cudaGetSymbolAddress(&p, g_W4lo); W4lo = (bf16*)p;
    cudaGetSymbolAddress(&p, g_H4);   H4   = (float*)p;
    cudaGetSymbolAddress(&p, g_Hfc);  Hfc  = (float*)p;

    // ---- preprocess (ncu captures launch #3 -> small bgemm_wide probe) ----
    deg_kernel<<<NN, 256>>>(adj, dinv);                                   // #0
    scale_adj_split<<<NN, 256>>>(adj, dinv, As, Ashi, Aslo);              // #1
    split_kernel<<<2048, 256>>>(W2, W2hi, W2lo, 5 * 1120 * 560);          // #2
    {
        // PROBE (#3): bgemm_wide mainloop sample, N=512 K=1024 (~18us).
        // Writes TB cols 0..511 (ldo 2240) - fully overwritten by w2 (cols
        // 0..559) before layer-3 reads. Deterministic.
        set_attrs_once();
        dim3 grid(4, 16);
        bgemm_wide<<<grid, 256, 2 * WSTG>>>(
            512, 1024, Ashi, Aslo, NN, Ashi, Aslo, NN,
            nullptr, nullptr, nullptr, nullptr, 2240,
            1.f, 0.f, 0.f, nullptr, 0, TBhi, TBlo, 2240, nullptr, 0);
    }
    split_kernel<<<1024, 256>>>(W3, W3hi, W3lo, 4 * 560 * 280);           // #4
    split_pad_kernel<<<256, 256>>>(W4, W4hi, W4lo, 3 * 280, 140, 144);    // #5

    // ---- layer 1 (cin=7, k=6): fp32 path ----
    copy_x_kernel<<<(NN * 7 + 255) / 256, 256>>>(x, Tw1);
    for (int i = 1; i < 6; i++) {
        float al = (i == 1) ? -1.f : -2.f, be = (i == 1) ? 1.f : 2.f;
        gemm_skinny<<<NN, 256>>>(7, NN, As, NN, Tw1 + (i - 1) * 7, 42,
                                 Tw1 + i * 7, 42, Tw1 + (i - 1) * 7,
                                 (i >= 2) ? Tw1 + (i - 2) * 7 : nullptr,
                                 nullptr, al, be, -1.f);
    }
    {
        dim3 g((1120 + 127) / 128, 32);
        sgemm_ep<<<g, 256>>>(NN, 1120, 42, Tw1, 42, W1, 1120,
                             nullptr, 0, b1, 1, TAhi, TAlo, 5600);
    }

    // ---- layers 2..4 : bf16 split mma path ----
    struct Cfg {
        int cin, cout, k, ldi, ldw, ldnext;
        bf16 *inhi, *inlo, *outhi, *outlo, *whi, *wlo;
        const float* bias;
    };
    Cfg L[3] = {
        {1120, 560, 5, 5600, 560, 2240, TAhi, TAlo, TBhi, TBlo, W2hi, W2lo, b2},
        {560, 280, 4, 2240, 280, 840, TBhi, TBlo, TAhi, TAlo, W3hi, W3lo, b3},
        {280, 140, 3, 840, 144, 0, TAhi, TAlo, nullptr, nullptr, W4hi, W4lo, b4},
    };
    for (int l = 0; l < 3; l++) {
        Cfg& c = L[l];
        for (int i = 1; i < c.k; i++) {
            float al = (i == 1) ? -1.f : -2.f, be = (i == 1) ? 1.f : 2.f;
            const bf16* Uh = c.inhi + (size_t)(i - 1) * c.cin;
            const bf16* Ul = c.inlo + (size_t)(i - 1) * c.cin;
            const bf16* Vh = (i >= 2) ? c.inhi + (size_t)(i - 2) * c.cin : nullptr;
            const bf16* Vl = (i >= 2) ? c.inlo + (size_t)(i - 2) * c.cin : nullptr;
            bgemm_launch(c.cin, NN, Ashi, Aslo, NN, Uh, Ul, c.ldi,
                         Uh, Ul, Vh, Vl, c.ldi, al, be, -1.f, nullptr, 0,
                         c.inhi + (size_t)i * c.cin, c.inlo + (size_t)i * c.cin,
                         c.ldi, nullptr, 0);
        }
        int K = c.k * c.cin;
        if (l < 2) {
            bgemm_launch(c.cout, K, c.inhi, c.inlo, c.ldi, c.whi, c.wlo, c.ldw,
                         nullptr, nullptr, nullptr, nullptr, c.ldnext,
                         1.f, 0.f, 0.f, c.bias, 1,
                         c.outhi, c.outlo, c.ldnext, nullptr, 0);
        } else {
            bgemm_launch(c.cout, K, c.inhi, c.inlo, c.ldi, c.whi, c.wlo, c.ldw,
                         nullptr, nullptr, nullptr, nullptr, 140,
                         1.f, 0.f, 0.f, c.bias, 1,
                         nullptr, nullptr, 0, H4, 140);
        }
    }

    // ---- FC layers (fp32) ----
    {
        dim3 g((140 + 127) / 128, 32);
        sgemm_ep<<<g, 256>>>(NN, 140, 140, H4, 140, fc1_w, 140, Hfc, 140,
                             fc1_b, 0, nullptr, nullptr, 0);
    }
    gemm_skinny<<<NN, 256>>>(4, 140, Hfc, 140, fc2_w, 4, out, 4,
                             nullptr, nullptr, fc2_b, 1.f, 0.f, 0.f);
}

// round 15
// speedup vs baseline: 1.1370x; 1.1370x over previous
#include <cuda_runtime.h>
#include <cuda_bf16.h>
#include <cstdint>

typedef __nv_bfloat16 bf16;

// ---------------------------------------------------------------------------
// ChebNet GCN forward, n=4096.  (sm_100 mma.sync path; issue-bound per ncu)
// Split bf16 (hi/lo), 3 cross terms, fp32 accum. M always 4096.
// bgemm_ep<NB>: 128xNBx32 tiles (NB=32/64/128 by N), cp.async 2-stage, ldmatrix.
// (bgemm_wide 64x64-warp variant measured SLOWER in R14 - 251 regs - removed.)
// ---------------------------------------------------------------------------

#define NN 4096

__device__ float g_As [(size_t)NN * NN];
__device__ bf16  g_AsHi[(size_t)NN * NN];
__device__ bf16  g_AsLo[(size_t)NN * NN];
__device__ float g_dinv[NN];
__device__ float g_Tw1[(size_t)NN * 42];
__device__ bf16  g_TAhi[(size_t)NN * 5600 + 256];
__device__ bf16  g_TAlo[(size_t)NN * 5600 + 256];
__device__ bf16  g_TBhi[(size_t)NN * 2240 + 256];
__device__ bf16  g_TBlo[(size_t)NN * 2240 + 256];
__device__ bf16  g_W2hi[5 * 1120 * 560 + 256], g_W2lo[5 * 1120 * 560 + 256];
__device__ bf16  g_W3hi[4 * 560 * 280 + 256],  g_W3lo[4 * 560 * 280 + 256];
__device__ bf16  g_W4hi[3 * 280 * 144 + 256],  g_W4lo[3 * 280 * 144 + 256];
__device__ float g_H4 [(size_t)NN * 140];
__device__ float g_Hfc[(size_t)NN * 140];

__device__ __forceinline__ void split_bf16(float r, bf16& hi, bf16& lo) {
    hi = __float2bfloat16_rn(r);
    lo = __float2bfloat16_rn(r - __bfloat162float(hi));
}

__device__ __forceinline__ uint32_t smem_u32(const void* p) {
    uint32_t a;
    asm("{ .reg .u64 t; cvta.to.shared.u64 t, %1; cvt.u32.u64 %0, t; }" : "=r"(a) : "l"(p));
    return a;
}
__device__ __forceinline__ void cpa16(uint32_t d, const void* s) {
    asm volatile("cp.async.cg.shared.global [%0], [%1], 16;" :: "r"(d), "l"(s));
}
#define CPA_COMMIT() asm volatile("cp.async.commit_group;" ::: "memory")
#define CPA_WAIT1()  asm volatile("cp.async.wait_group 1;" ::: "memory")
#define CPA_WAIT0()  asm volatile("cp.async.wait_group 0;" ::: "memory")
#define LDSM4(r0, r1, r2, r3, a)                                              \
    asm volatile("ldmatrix.sync.aligned.m8n8.x4.shared.b16 {%0,%1,%2,%3}, [%4];" \
                 : "=r"(r0), "=r"(r1), "=r"(r2), "=r"(r3) : "r"(a))
#define LDSM4T(r0, r1, r2, r3, a)                                             \
    asm volatile("ldmatrix.sync.aligned.m8n8.x4.trans.shared.b16 {%0,%1,%2,%3}, [%4];" \
                 : "=r"(r0), "=r"(r1), "=r"(r2), "=r"(r3) : "r"(a))
#define MMA16816(d, a0, a1, a2, a3, b0, b1)                                   \
    asm volatile(                                                              \
        "mma.sync.aligned.m16n8k16.row.col.f32.bf16.bf16.f32 "                 \
        "{%0,%1,%2,%3}, {%4,%5,%6,%7}, {%8,%9}, {%0,%1,%2,%3};"                \
        : "+f"(d[0]), "+f"(d[1]), "+f"(d[2]), "+f"(d[3])                       \
        : "r"(a0), "r"(a1), "r"(a2), "r"(a3), "r"(b0), "r"(b1))

// ------------------------------ small kernels ------------------------------

__global__ void deg_kernel(const float* __restrict__ adj, float* __restrict__ dinv) {
    int r = blockIdx.x;
    const float* row = adj + (size_t)r * NN;
    float s = 0.f;
    for (int c = threadIdx.x; c < NN; c += blockDim.x) s += row[c];
    __shared__ float sh[256];
    sh[threadIdx.x] = s;
    __syncthreads();
    for (int o = 128; o > 0; o >>= 1) {
        if (threadIdx.x < o) sh[threadIdx.x] += sh[threadIdx.x + o];
        __syncthreads();
    }
    if (threadIdx.x == 0) dinv[r] = rsqrtf(fmaxf(sh[0], 1e-12f));
}

__global__ void scale_adj_split(const float* __restrict__ adj,
                                const float* __restrict__ dinv,
                                float* __restrict__ As,
                                bf16* __restrict__ hi, bf16* __restrict__ lo) {
    int r = blockIdx.x;
    float dr = dinv[r];
    size_t base = (size_t)r * NN;
    for (int c = threadIdx.x; c < NN; c += blockDim.x) {
        float v = adj[base + c] * dr * dinv[c];
        As[base + c] = v;
        bf16 h, l;
        split_bf16(v, h, l);
        hi[base + c] = h;
        lo[base + c] = l;
    }
}

__global__ void split_kernel(const float* __restrict__ src,
                             bf16* __restrict__ hi, bf16* __restrict__ lo, int n) {
    for (int i = blockIdx.x * blockDim.x + threadIdx.x; i < n;
         i += gridDim.x * blockDim.x) {
        bf16 h, l;
        split_bf16(src[i], h, l);
        hi[i] = h;
        lo[i] = l;
    }
}

__global__ void split_pad_kernel(const float* __restrict__ W,
                                 bf16* __restrict__ hi, bf16* __restrict__ lo,
                                 int rows, int cout, int ldp) {
    int tot = rows * ldp;
    for (int i = blockIdx.x * blockDim.x + threadIdx.x; i < tot;
         i += gridDim.x * blockDim.x) {
        int co = i % ldp, r = i / ldp;
        float v = (co < cout) ? W[(size_t)r * cout + co] : 0.f;
        bf16 h, l;
        split_bf16(v, h, l);
        hi[i] = h;
        lo[i] = l;
    }
}

__global__ void copy_x_kernel(const float* __restrict__ x, float* __restrict__ Tw1) {
    int i = blockIdx.x * blockDim.x + threadIdx.x;
    if (i < NN * 7) Tw1[(size_t)(i / 7) * 42 + (i % 7)] = x[i];
}

// ------------------- skinny fp32 GEMM (layer-1 cheb, FC2) -------------------
#define SKN 8
__global__ __launch_bounds__(256)
void gemm_skinny(int N, int K,
                 const float* __restrict__ A, int lda,
                 const float* __restrict__ B, int ldb,
                 float* __restrict__ C, int ldc,
                 const float* __restrict__ U, const float* __restrict__ V,
                 const float* __restrict__ bias,
                 float alpha, float beta, float gamma) {
    const int row = blockIdx.x, tid = threadIdx.x;
    const float* Arow = A + (size_t)row * lda;
    float acc[SKN];
#pragma unroll
    for (int j = 0; j < SKN; j++) acc[j] = 0.f;
    for (int k = tid; k < K; k += 256) {
        float a = Arow[k];
        const float* Bk = B + (size_t)k * ldb;
#pragma unroll
        for (int j = 0; j < SKN; j++)
            if (j < N) acc[j] += a * Bk[j];
    }
#pragma unroll
    for (int j = 0; j < SKN; j++)
#pragma unroll
        for (int o = 16; o > 0; o >>= 1)
            acc[j] += __shfl_xor_sync(0xFFFFFFFFu, acc[j], o);
    __shared__ float red[8][SKN];
    int wid = tid >> 5, lane = tid & 31;
    if (lane == 0)
#pragma unroll
        for (int j = 0; j < SKN; j++) red[wid][j] = acc[j];
    __syncthreads();
    if (tid < N) {
        float s = 0.f;
#pragma unroll
        for (int w = 0; w < 8; w++) s += red[w][tid];
        size_t idx = (size_t)row * ldc + tid;
        float r = alpha * s;
        if (U) r += beta * U[idx];
        if (V) r += gamma * V[idx];
        if (bias) r += bias[tid];
        C[idx] = r;
    }
}

// ----------------------- fp32 SIMT GEMM (layer-1 weight, FC1) ---------------
__global__ __launch_bounds__(256)
void sgemm_ep(int M, int N, int K,
              const float* __restrict__ A, int lda,
              const float* __restrict__ B, int ldb,
              float* __restrict__ C, int ldc,
              const float* __restrict__ bias, int relu,
              bf16* __restrict__ Ohi, bf16* __restrict__ Olo, int ldo) {
    __shared__ float As_s[8][132];
    __shared__ float Bs_s[8][132];
    const int tid = threadIdx.x, tx = tid % 16, ty = tid / 16;
    const int row0 = blockIdx.y * 128, col0 = blockIdx.x * 128;
    float acc[8][8];
#pragma unroll
    for (int i = 0; i < 8; i++)
#pragma unroll
        for (int j = 0; j < 8; j++) acc[i][j] = 0.f;
    const int lane32 = tid % 32, bkk = tid / 32;
    for (int k0 = 0; k0 < K; k0 += 8) {
#pragma unroll
        for (int j = 0; j < 4; j++) {
            int e = tid + 256 * j, ar = e >> 3, ak = e & 7;
            int m = row0 + ar, k = k0 + ak;
            As_s[ak][ar] = (m < M && k < K) ? A[(size_t)m * lda + k] : 0.f;
        }
#pragma unroll
        for (int j = 0; j < 4; j++) {
            int n = col0 + lane32 + 32 * j, k = k0 + bkk;
            Bs_s[bkk][lane32 + 32 * j] = (k < K && n < N) ? B[(size_t)k * ldb + n] : 0.f;
        }
        __syncthreads();
#pragma unroll
        for (int kk = 0; kk < 8; kk++) {
            float af[8], bf[8];
#pragma unroll
            for (int i = 0; i < 8; i++) af[i] = As_s[kk][ty * 8 + i];
#pragma unroll
            for (int j = 0; j < 8; j++) bf[j] = Bs_s[kk][tx * 8 + j];
#pragma unroll
            for (int i = 0; i < 8; i++)
#pragma unroll
                for (int j = 0; j < 8; j++) acc[i][j] += af[i] * bf[j];
        }
        __syncthreads();
    }
#pragma unroll
    for (int i = 0; i < 8; i++) {
        int m = row0 + ty * 8 + i;
        if (m >= M) continue;
#pragma unroll
        for (int j = 0; j < 8; j++) {
            int n = col0 + tx * 8 + j;
            if (n >= N) continue;
            float r = acc[i][j];
            if (bias) r += bias[n];
            if (relu) r = fmaxf(r, 0.f);
            if (C) C[(size_t)m * ldc + n] = r;
            if (Ohi) {
                bf16 h, l;
                split_bf16(r, h, l);
                Ohi[(size_t)m * ldo + n] = h;
                Olo[(size_t)m * ldo + n] = l;
            }
        }
    }
}

// --------------------- bf16 split mma GEMM, 128xNB tiles --------------------

template <int NB>
__global__ __launch_bounds__(256, 2)
void bgemm_ep(int N, int K,
              const bf16* __restrict__ Ahi, const bf16* __restrict__ Alo, long lda,
              const bf16* __restrict__ Bhi, const bf16* __restrict__ Blo, long ldb,
              const bf16* __restrict__ Uhi, const bf16* __restrict__ Ulo,
              const bf16* __restrict__ Vhi, const bf16* __restrict__ Vlo, long ldu,
              float alpha, float beta, float gamma,
              const float* __restrict__ bias, int relu,
              bf16* __restrict__ Ohi, bf16* __restrict__ Olo, long ldo,
              float* __restrict__ Cf, long ldc) {
    constexpr int BROW = NB + 8;
    constexpr int BPL = 32 * BROW * 2;
    constexpr int STG = 20480 + 2 * BPL;
    constexpr int BSEGS = 32 * (NB / 8);       // B segs per plane
    extern __shared__ char smem[];
    const uint32_t sb = smem_u32(smem);
    const int tid = threadIdx.x, lane = tid & 31, wid = tid >> 5;
    const int wr = wid & 3, wc = wid >> 2;
    const int g = lane >> 2, t4 = lane & 3;
    const int t8 = lane & 7, quad = lane >> 3;
    const int row0 = blockIdx.y * 128, col0 = blockIdx.x * NB;
    const int NC = (K + 31) >> 5;

    float acc[2][NB / 16][4];
#pragma unroll
    for (int i = 0; i < 2; i++)
#pragma unroll
        for (int j = 0; j < NB / 16; j++)
#pragma unroll
            for (int e = 0; e < 4; e++) acc[i][j][e] = 0.f;

    auto load_stage = [&](int st, int c) {
        const long k0 = (long)c << 5;
        char* base = smem + st * STG;
#pragma unroll
        for (int q = 0; q < 2; q++) {
            int seg = tid * 2 + q;
            int row = seg >> 2, k8 = (seg & 3) << 3;
            char* da = base + 2 * (row * 40 + k8);
            if (k0 + k8 < K) {
                cpa16(smem_u32(da), Ahi + (size_t)(row0 + row) * lda + k0 + k8);
                cpa16(smem_u32(da + 10240), Alo + (size_t)(row0 + row) * lda + k0 + k8);
            } else {
                *(uint4*)da = make_uint4(0u, 0u, 0u, 0u);
                *(uint4*)(da + 10240) = make_uint4(0u, 0u, 0u, 0u);
            }
        }
        // B loader: generic over NB (NB=32: 128 segs -> threads < 128)
#pragma unroll
        for (int q = 0; q < (BSEGS + 255) / 256; q++) {
            int seg = tid + q * 256;
            if (seg < BSEGS) {
                int row = seg / (NB / 8), n8 = (seg % (NB / 8)) << 3;
                char* db = base + 20480 + 2 * (row * BROW + n8);
                if (k0 + row < K) {
                    cpa16(smem_u32(db), Bhi + (size_t)(k0 + row) * ldb + col0 + n8);
                    cpa16(smem_u32(db + BPL), Blo + (size_t)(k0 + row) * ldb + col0 + n8);
                } else {
                    *(uint4*)db = make_uint4(0u, 0u, 0u, 0u);
                    *(uint4*)(db + BPL) = make_uint4(0u, 0u, 0u, 0u);
                }
            }
        }
    };

    load_stage(0, 0);
    CPA_COMMIT();
    if (NC > 1) load_stage(1, 1);
    CPA_COMMIT();

    const int arow = wr * 32 + ((quad & 1) << 3) + t8;
    const int acol = (quad & 2) << 2;
    const int brow = ((quad & 1) << 3) + t8;
    const int bcol = wc * (NB / 2) + ((quad & 2) << 2);

    for (int c = 0; c < NC; c++) {
        if (c < NC - 1) CPA_WAIT1(); else CPA_WAIT0();
        __syncthreads();
        const uint32_t s0 = sb + (uint32_t)((c & 1) * STG);
        const uint32_t aB = s0, bB = s0 + 20480;
#pragma unroll
        for (int kh = 0; kh < 2; kh++) {
            uint32_t ah[2][4], al[2][4];
#pragma unroll
            for (int mi = 0; mi < 2; mi++) {
                uint32_t adr = aB + 2 * ((arow + mi * 16) * 40 + acol + kh * 16);
                LDSM4(ah[mi][0], ah[mi][1], ah[mi][2], ah[mi][3], adr);
                LDSM4(al[mi][0], al[mi][1], al[mi][2], al[mi][3], adr + 10240);
            }
#pragma unroll
            for (int p = 0; p < NB / 32; p++) {
                uint32_t bh[4], bl[4];
                uint32_t bdr = bB + 2 * ((brow + kh * 16) * BROW + bcol + p * 16);
                LDSM4T(bh[0], bh[1], bh[2], bh[3], bdr);
                LDSM4T(bl[0], bl[1], bl[2], bl[3], bdr + BPL);
#pragma unroll
                for (int mi = 0; mi < 2; mi++) {
                    MMA16816(acc[mi][2 * p], ah[mi][0], ah[mi][1], ah[mi][2], ah[mi][3], bh[0], bh[1]);
                    MMA16816(acc[mi][2 * p], ah[mi][0], ah[mi][1], ah[mi][2], ah[mi][3], bl[0], bl[1]);
                    MMA16816(acc[mi][2 * p], al[mi][0], al[mi][1], al[mi][2], al[mi][3], bh[0], bh[1]);
                    MMA16816(acc[mi][2 * p + 1], ah[mi][0], ah[mi][1], ah[mi][2], ah[mi][3], bh[2], bh[3]);
                    MMA16816(acc[mi][2 * p + 1], ah[mi][0], ah[mi][1], ah[mi][2], ah[mi][3], bl[2], bl[3]);
                    MMA16816(acc[mi][2 * p + 1], al[mi][0], al[mi][1], al[mi][2], al[mi][3], bh[2], bh[3]);
                }
            }
        }
        __syncthreads();
        if (c + 2 < NC) { load_stage(c & 1, c + 2); CPA_COMMIT(); }
    }

#pragma unroll
    for (int mi = 0; mi < 2; mi++) {
        int rb = row0 + wr * 32 + mi * 16 + g;
#pragma unroll
        for (int ni = 0; ni < NB / 16; ni++) {
            int cb = col0 + wc * (NB / 2) + ni * 8 + 2 * t4;
#pragma unroll
            for (int e = 0; e < 4; e++) {
                int rr = rb + ((e >> 1) << 3);
                int cc = cb + (e & 1);
                if (cc >= N) continue;
                float r = alpha * acc[mi][ni][e];
                size_t iu = (size_t)rr * ldu + cc;
                if (Uhi) r += beta * (__bfloat162float(Uhi[iu]) + __bfloat162float(Ulo[iu]));
                if (Vhi) r += gamma * (__bfloat162float(Vhi[iu]) + __bfloat162float(Vlo[iu]));
                if (bias) r += bias[cc];
                if (relu) r = fmaxf(r, 0.f);
                if (Cf) Cf[(size_t)rr * ldc + cc] = r;
                if (Ohi) {
                    bf16 h, l;
                    split_bf16(r, h, l);
                    Ohi[(size_t)rr * ldo + cc] = h;
                    Olo[(size_t)rr * ldo + cc] = l;
                }
            }
        }
    }
}

// ------------------------------- host side ----------------------------------

#define STG128 37888
#define STG64  29696
#define STG32  25600

static void set_attrs_once() {
    static int done = 0;
    if (!done) {
        cudaFuncSetAttribute(bgemm_ep<128>, cudaFuncAttributeMaxDynamicSharedMemorySize, 2 * STG128);
        cudaFuncSetAttribute(bgemm_ep<64>, cudaFuncAttributeMaxDynamicSharedMemorySize, 2 * STG64);
        cudaFuncSetAttribute(bgemm_ep<32>, cudaFuncAttributeMaxDynamicSharedMemorySize, 2 * STG32);
        done = 1;
    }
}

static inline void bgemm_launch(int N, int K,
                                const bf16* Ahi, const bf16* Alo, long lda,
                                const bf16* Bhi, const bf16* Blo, long ldb,
                                const bf16* Uhi, const bf16* Ulo,
                                const bf16* Vhi, const bf16* Vlo, long ldu,
                                float al, float be, float ga,
                                const float* bias, int relu,
                                bf16* Ohi, bf16* Olo, long ldo,
                                float* Cf, long ldc) {
    set_attrs_once();
    if (N <= 280) {
        dim3 grid((N + 31) / 32, 32);
        bgemm_ep<32><<<grid, 256, 2 * STG32>>>(N, K, Ahi, Alo, lda, Bhi, Blo, ldb,
                                               Uhi, Ulo, Vhi, Vlo, ldu, al, be, ga,
                                               bias, relu, Ohi, Olo, ldo, Cf, ldc);
    } else if (N <= 560) {
        dim3 grid((N + 63) / 64, 32);
        bgemm_ep<64><<<grid, 256, 2 * STG64>>>(N, K, Ahi, Alo, lda, Bhi, Blo, ldb,
                                               Uhi, Ulo, Vhi, Vlo, ldu, al, be, ga,
                                               bias, relu, Ohi, Olo, ldo, Cf, ldc);
    } else {
        dim3 grid((N + 127) / 128, 32);
        bgemm_ep<128><<<grid, 256, 2 * STG128>>>(N, K, Ahi, Alo, lda, Bhi, Blo, ldb,
                                                 Uhi, Ulo, Vhi, Vlo, ldu, al, be, ga,
                                                 bias, relu, Ohi, Olo, ldo, Cf, ldc);
    }
}

extern "C" void kernel_launch(void* const* d_in, const int* in_sizes, int n_in,
                              void* d_out, int out_size) {
    const float* x     = (const float*)d_in[0];
    const float* adj   = (const float*)d_in[1];
    const float* W1    = (const float*)d_in[2];
    const float* b1    = (const float*)d_in[3];
    const float* W2    = (const float*)d_in[4];
    const float* b2    = (const float*)d_in[5];
    const float* W3    = (const float*)d_in[6];
    const float* b3    = (const float*)d_in[7];
    const float* W4    = (const float*)d_in[8];
    const float* b4    = (const float*)d_in[9];
    const float* fc1_w = (const float*)d_in[10];
    const float* fc1_b = (const float*)d_in[11];
    const float* fc2_w = (const float*)d_in[12];
    const float* fc2_b = (const float*)d_in[13];
    float* out = (float*)d_out;

    void* p;
    float *As, *dinv, *Tw1, *H4, *Hfc;
    bf16 *Ashi, *Aslo, *TAhi, *TAlo, *TBhi, *TBlo;
    bf16 *W2hi, *W2lo, *W3hi, *W3lo, *W4hi, *W4lo;
    cudaGetSymbolAddress(&p, g_As);   As   = (float*)p;
    cudaGetSymbolAddress(&p, g_AsHi); Ashi = (bf16*)p;
    cudaGetSymbolAddress(&p, g_AsLo); Aslo = (bf16*)p;
    cudaGetSymbolAddress(&p, g_dinv); dinv = (float*)p;
    cudaGetSymbolAddress(&p, g_Tw1);  Tw1  = (float*)p;
    cudaGetSymbolAddress(&p, g_TAhi); TAhi = (bf16*)p;
    cudaGetSymbolAddress(&p, g_TAlo); TAlo = (bf16*)p;
    cudaGetSymbolAddress(&p, g_TBhi); TBhi = (bf16*)p;
    cudaGetSymbolAddress(&p, g_TBlo); TBlo = (bf16*)p;
    cudaGetSymbolAddress(&p, g_W2hi); W2hi = (bf16*)p;
    cudaGetSymbolAddress(&p, g_W2lo); W2lo = (bf16*)p;
    cudaGetSymbolAddress(&p, g_W3hi); W3hi = (bf16*)p;
    cudaGetSymbolAddress(&p, g_W3lo); W3lo = (bf16*)p;
    cudaGetSymbolAddress(&p, g_W4hi); W4hi = (bf16*)p;
    cudaGetSymbolAddress(&p, g_W4lo); W4lo = (bf16*)p;
    cudaGetSymbolAddress(&p, g_H4);   H4   = (float*)p;
    cudaGetSymbolAddress(&p, g_Hfc);  Hfc  = (float*)p;

    // ---- preprocess (ncu captures launch #3 -> small bgemm_ep probe) ----
    deg_kernel<<<NN, 256>>>(adj, dinv);                                   // #0
    scale_adj_split<<<NN, 256>>>(adj, dinv, As, Ashi, Aslo);              // #1
    split_kernel<<<2048, 256>>>(W2, W2hi, W2lo, 5 * 1120 * 560);          // #2
    {
        // PROBE (#3): bgemm_ep<128> mainloop sample, N=128 K=512 (~28us).
        // Writes TB cols 0..127 (ldo 2240) - fully overwritten by w2 (cols
        // 0..559) before layer-3 reads. Deterministic.
        set_attrs_once();
        dim3 grid(1, 32);
        bgemm_ep<128><<<grid, 256, 2 * STG128>>>(
            128, 512, Ashi, Aslo, NN, Ashi, Aslo, NN,
            nullptr, nullptr, nullptr, nullptr, 2240,
            1.f, 0.f, 0.f, nullptr, 0, TBhi, TBlo, 2240, nullptr, 0);
    }
    split_kernel<<<1024, 256>>>(W3, W3hi, W3lo, 4 * 560 * 280);           // #4
    split_pad_kernel<<<256, 256>>>(W4, W4hi, W4lo, 3 * 280, 140, 144);    // #5

    // ---- layer 1 (cin=7, k=6): fp32 path ----
    copy_x_kernel<<<(NN * 7 + 255) / 256, 256>>>(x, Tw1);
    for (int i = 1; i < 6; i++) {
        float al = (i == 1) ? -1.f : -2.f, be = (i == 1) ? 1.f : 2.f;
        gemm_skinny<<<NN, 256>>>(7, NN, As, NN, Tw1 + (i - 1) * 7, 42,
                                 Tw1 + i * 7, 42, Tw1 + (i - 1) * 7,
                                 (i >= 2) ? Tw1 + (i - 2) * 7 : nullptr,
                                 nullptr, al, be, -1.f);
    }
    {
        dim3 g((1120 + 127) / 128, 32);
        sgemm_ep<<<g, 256>>>(NN, 1120, 42, Tw1, 42, W1, 1120,
                             nullptr, 0, b1, 1, TAhi, TAlo, 5600);
    }

    // ---- layers 2..4 : bf16 split mma path ----
    struct Cfg {
        int cin, cout, k, ldi, ldw, ldnext;
        bf16 *inhi, *inlo, *outhi, *outlo, *whi, *wlo;
        const float* bias;
    };
    Cfg L[3] = {
        {1120, 560, 5, 5600, 560, 2240, TAhi, TAlo, TBhi, TBlo, W2hi, W2lo, b2},
        {560, 280, 4, 2240, 280, 840, TBhi, TBlo, TAhi, TAlo, W3hi, W3lo, b3},
        {280, 140, 3, 840, 144, 0, TAhi, TAlo, nullptr, nullptr, W4hi, W4lo, b4},
    };
    for (int l = 0; l < 3; l++) {
        Cfg& c = L[l];
        for (int i = 1; i < c.k; i++) {
            float al = (i == 1) ? -1.f : -2.f, be = (i == 1) ? 1.f : 2.f;
            const bf16* Uh = c.inhi + (size_t)(i - 1) * c.cin;
            const bf16* Ul = c.inlo + (size_t)(i - 1) * c.cin;
            const bf16* Vh = (i >= 2) ? c.inhi + (size_t)(i - 2) * c.cin : nullptr;
            const bf16* Vl = (i >= 2) ? c.inlo + (size_t)(i - 2) * c.cin : nullptr;
            bgemm_launch(c.cin, NN, Ashi, Aslo, NN, Uh, Ul, c.ldi,
                         Uh, Ul, Vh, Vl, c.ldi, al, be, -1.f, nullptr, 0,
                         c.inhi + (size_t)i * c.cin, c.inlo + (size_t)i * c.cin,
                         c.ldi, nullptr, 0);
        }
        int K = c.k * c.cin;
        if (l < 2) {
            bgemm_launch(c.cout, K, c.inhi, c.inlo, c.ldi, c.whi, c.wlo, c.ldw,
                         nullptr, nullptr, nullptr, nullptr, c.ldnext,
                         1.f, 0.f, 0.f, c.bias, 1,
                         c.outhi, c.outlo, c.ldnext, nullptr, 0);
        } else {
            bgemm_launch(c.cout, K, c.inhi, c.inlo, c.ldi, c.whi, c.wlo, c.ldw,
                         nullptr, nullptr, nullptr, nullptr, 140,
                         1.f, 0.f, 0.f, c.bias, 1,
                         nullptr, nullptr, 0, H4, 140);
        }
    }

    // ---- FC layers (fp32) ----
    {
        dim3 g((140 + 127) / 128, 32);
        sgemm_ep<<<g, 256>>>(NN, 140, 140, H4, 140, fc1_w, 140, Hfc, 140,
                             fc1_b, 0, nullptr, nullptr, 0);
    }
    gemm_skinny<<<NN, 256>>>(4, 140, Hfc, 140, fc2_w, 4, out, 4,
                             nullptr, nullptr, fc2_b, 1.f, 0.f, 0.f);
}

// round 16
// speedup vs baseline: 1.1848x; 1.0421x over previous
#include <cuda_runtime.h>
#include <cuda_bf16.h>
#include <cstdint>

typedef __nv_bfloat16 bf16;

// ---------------------------------------------------------------------------
// ChebNet GCN forward, n=4096.  (sm_100 mma.sync path; issue-bound per ncu)
// Split bf16 (hi/lo), 3 cross terms, fp32 accum. M always 4096.
// bgemm_ep<NB>: 128xNBx32 tiles (NB=32/64/128 by N), cp.async 2-stage, ldmatrix.
// Layer-1 (cin=7) runs a skinny fp32-accum path reading the bf16 As planes.
// ---------------------------------------------------------------------------

#define NN 4096

__device__ bf16  g_AsHi[(size_t)NN * NN];
__device__ bf16  g_AsLo[(size_t)NN * NN];
__device__ float g_dinv[NN];
__device__ float g_Tw1[(size_t)NN * 42];
__device__ bf16  g_TAhi[(size_t)NN * 5600 + 256];
__device__ bf16  g_TAlo[(size_t)NN * 5600 + 256];
__device__ bf16  g_TBhi[(size_t)NN * 2240 + 256];
__device__ bf16  g_TBlo[(size_t)NN * 2240 + 256];
__device__ bf16  g_W2hi[5 * 1120 * 560 + 256], g_W2lo[5 * 1120 * 560 + 256];
__device__ bf16  g_W3hi[4 * 560 * 280 + 256],  g_W3lo[4 * 560 * 280 + 256];
__device__ bf16  g_W4hi[3 * 280 * 144 + 256],  g_W4lo[3 * 280 * 144 + 256];
__device__ float g_H4 [(size_t)NN * 140];
__device__ float g_Hfc[(size_t)NN * 140];

__device__ __forceinline__ void split_bf16(float r, bf16& hi, bf16& lo) {
    hi = __float2bfloat16_rn(r);
    lo = __float2bfloat16_rn(r - __bfloat162float(hi));
}

__device__ __forceinline__ uint32_t smem_u32(const void* p) {
    uint32_t a;
    asm("{ .reg .u64 t; cvta.to.shared.u64 t, %1; cvt.u32.u64 %0, t; }" : "=r"(a) : "l"(p));
    return a;
}
__device__ __forceinline__ void cpa16(uint32_t d, const void* s) {
    asm volatile("cp.async.cg.shared.global [%0], [%1], 16;" :: "r"(d), "l"(s));
}
#define CPA_COMMIT() asm volatile("cp.async.commit_group;" ::: "memory")
#define CPA_WAIT1()  asm volatile("cp.async.wait_group 1;" ::: "memory")
#define CPA_WAIT0()  asm volatile("cp.async.wait_group 0;" ::: "memory")
#define LDSM4(r0, r1, r2, r3, a)                                              \
    asm volatile("ldmatrix.sync.aligned.m8n8.x4.shared.b16 {%0,%1,%2,%3}, [%4];" \
                 : "=r"(r0), "=r"(r1), "=r"(r2), "=r"(r3) : "r"(a))
#define LDSM4T(r0, r1, r2, r3, a)                                             \
    asm volatile("ldmatrix.sync.aligned.m8n8.x4.trans.shared.b16 {%0,%1,%2,%3}, [%4];" \
                 : "=r"(r0), "=r"(r1), "=r"(r2), "=r"(r3) : "r"(a))
#define MMA16816(d, a0, a1, a2, a3, b0, b1)                                   \
    asm volatile(                                                              \
        "mma.sync.aligned.m16n8k16.row.col.f32.bf16.bf16.f32 "                 \
        "{%0,%1,%2,%3}, {%4,%5,%6,%7}, {%8,%9}, {%0,%1,%2,%3};"                \
        : "+f"(d[0]), "+f"(d[1]), "+f"(d[2]), "+f"(d[3])                       \
        : "r"(a0), "r"(a1), "r"(a2), "r"(a3), "r"(b0), "r"(b1))

// ------------------------------ small kernels ------------------------------

__global__ void deg_kernel(const float* __restrict__ adj, float* __restrict__ dinv) {
    int r = blockIdx.x;
    const float* row = adj + (size_t)r * NN;
    float s = 0.f;
    for (int c = threadIdx.x; c < NN; c += blockDim.x) s += row[c];
    __shared__ float sh[256];
    sh[threadIdx.x] = s;
    __syncthreads();
    for (int o = 128; o > 0; o >>= 1) {
        if (threadIdx.x < o) sh[threadIdx.x] += sh[threadIdx.x + o];
        __syncthreads();
    }
    if (threadIdx.x == 0) dinv[r] = rsqrtf(fmaxf(sh[0], 1e-12f));
}

__global__ void scale_adj_split(const float* __restrict__ adj,
                                const float* __restrict__ dinv,
                                bf16* __restrict__ hi, bf16* __restrict__ lo) {
    int r = blockIdx.x;
    float dr = dinv[r];
    size_t base = (size_t)r * NN;
    for (int c = threadIdx.x; c < NN; c += blockDim.x) {
        float v = adj[base + c] * dr * dinv[c];
        bf16 h, l;
        split_bf16(v, h, l);
        hi[base + c] = h;
        lo[base + c] = l;
    }
}

__global__ void split_kernel(const float* __restrict__ src,
                             bf16* __restrict__ hi, bf16* __restrict__ lo, int n) {
    for (int i = blockIdx.x * blockDim.x + threadIdx.x; i < n;
         i += gridDim.x * blockDim.x) {
        bf16 h, l;
        split_bf16(src[i], h, l);
        hi[i] = h;
        lo[i] = l;
    }
}

__global__ void split_pad_kernel(const float* __restrict__ W,
                                 bf16* __restrict__ hi, bf16* __restrict__ lo,
                                 int rows, int cout, int ldp) {
    int tot = rows * ldp;
    for (int i = blockIdx.x * blockDim.x + threadIdx.x; i < tot;
         i += gridDim.x * blockDim.x) {
        int co = i % ldp, r = i / ldp;
        float v = (co < cout) ? W[(size_t)r * cout + co] : 0.f;
        bf16 h, l;
        split_bf16(v, h, l);
        hi[i] = h;
        lo[i] = l;
    }
}

__global__ void copy_x_kernel(const float* __restrict__ x, float* __restrict__ Tw1) {
    int i = blockIdx.x * blockDim.x + threadIdx.x;
    if (i < NN * 7) Tw1[(size_t)(i / 7) * 42 + (i % 7)] = x[i];
}

// ------------- skinny GEMM, A = bf16 hi/lo planes (layer-1 cheb) ------------
#define SKN 8
__global__ __launch_bounds__(256)
void gemm_skinny_pk(int N, int K,
                    const bf16* __restrict__ Ah, const bf16* __restrict__ Al,
                    long lda,
                    const float* __restrict__ B, int ldb,
                    float* __restrict__ C, int ldc,
                    const float* __restrict__ U, const float* __restrict__ V,
                    float alpha, float beta, float gamma) {
    const int row = blockIdx.x, tid = threadIdx.x;
    const bf16* Arh = Ah + (size_t)row * lda;
    const bf16* Arl = Al + (size_t)row * lda;
    float acc[SKN];
#pragma unroll
    for (int j = 0; j < SKN; j++) acc[j] = 0.f;
    for (int k = tid; k < K; k += 256) {
        float a = __bfloat162float(Arh[k]) + __bfloat162float(Arl[k]);
        const float* Bk = B + (size_t)k * ldb;
#pragma unroll
        for (int j = 0; j < SKN; j++)
            if (j < N) acc[j] += a * Bk[j];
    }
#pragma unroll
    for (int j = 0; j < SKN; j++)
#pragma unroll
        for (int o = 16; o > 0; o >>= 1)
            acc[j] += __shfl_xor_sync(0xFFFFFFFFu, acc[j], o);
    __shared__ float red[8][SKN];
    int wid = tid >> 5, lane = tid & 31;
    if (lane == 0)
#pragma unroll
        for (int j = 0; j < SKN; j++) red[wid][j] = acc[j];
    __syncthreads();
    if (tid < N) {
        float s = 0.f;
#pragma unroll
        for (int w = 0; w < 8; w++) s += red[w][tid];
        size_t idx = (size_t)row * ldc + tid;
        float r = alpha * s;
        if (U) r += beta * U[idx];
        if (V) r += gamma * V[idx];
        C[idx] = r;
    }
}

// ------------------- skinny fp32 GEMM (FC2) ---------------------------------
__global__ __launch_bounds__(256)
void gemm_skinny(int N, int K,
                 const float* __restrict__ A, int lda,
                 const float* __restrict__ B, int ldb,
                 float* __restrict__ C, int ldc,
                 const float* __restrict__ bias) {
    const int row = blockIdx.x, tid = threadIdx.x;
    const float* Arow = A + (size_t)row * lda;
    float acc[SKN];
#pragma unroll
    for (int j = 0; j < SKN; j++) acc[j] = 0.f;
    for (int k = tid; k < K; k += 256) {
        float a = Arow[k];
        const float* Bk = B + (size_t)k * ldb;
#pragma unroll
        for (int j = 0; j < SKN; j++)
            if (j < N) acc[j] += a * Bk[j];
    }
#pragma unroll
    for (int j = 0; j < SKN; j++)
#pragma unroll
        for (int o = 16; o > 0; o >>= 1)
            acc[j] += __shfl_xor_sync(0xFFFFFFFFu, acc[j], o);
    __shared__ float red[8][SKN];
    int wid = tid >> 5, lane = tid & 31;
    if (lane == 0)
#pragma unroll
        for (int j = 0; j < SKN; j++) red[wid][j] = acc[j];
    __syncthreads();
    if (tid < N) {
        float s = 0.f;
#pragma unroll
        for (int w = 0; w < 8; w++) s += red[w][tid];
        float r = s;
        if (bias) r += bias[tid];
        C[(size_t)row * ldc + tid] = r;
    }
}

// ----------------------- fp32 SIMT GEMM (layer-1 weight, FC1) ---------------
__global__ __launch_bounds__(256)
void sgemm_ep(int M, int N, int K,
              const float* __restrict__ A, int lda,
              const float* __restrict__ B, int ldb,
              float* __restrict__ C, int ldc,
              const float* __restrict__ bias, int relu,
              bf16* __restrict__ Ohi, bf16* __restrict__ Olo, int ldo) {
    __shared__ float As_s[8][132];
    __shared__ float Bs_s[8][132];
    const int tid = threadIdx.x, tx = tid % 16, ty = tid / 16;
    const int row0 = blockIdx.y * 128, col0 = blockIdx.x * 128;
    float acc[8][8];
#pragma unroll
    for (int i = 0; i < 8; i++)
#pragma unroll
        for (int j = 0; j < 8; j++) acc[i][j] = 0.f;
    const int lane32 = tid % 32, bkk = tid / 32;
    for (int k0 = 0; k0 < K; k0 += 8) {
#pragma unroll
        for (int j = 0; j < 4; j++) {
            int e = tid + 256 * j, ar = e >> 3, ak = e & 7;
            int m = row0 + ar, k = k0 + ak;
            As_s[ak][ar] = (m < M && k < K) ? A[(size_t)m * lda + k] : 0.f;
        }
#pragma unroll
        for (int j = 0; j < 4; j++) {
            int n = col0 + lane32 + 32 * j, k = k0 + bkk;
            Bs_s[bkk][lane32 + 32 * j] = (k < K && n < N) ? B[(size_t)k * ldb + n] : 0.f;
        }
        __syncthreads();
#pragma unroll
        for (int kk = 0; kk < 8; kk++) {
            float af[8], bf[8];
#pragma unroll
            for (int i = 0; i < 8; i++) af[i] = As_s[kk][ty * 8 + i];
#pragma unroll
            for (int j = 0; j < 8; j++) bf[j] = Bs_s[kk][tx * 8 + j];
#pragma unroll
            for (int i = 0; i < 8; i++)
#pragma unroll
                for (int j = 0; j < 8; j++) acc[i][j] += af[i] * bf[j];
        }
        __syncthreads();
    }
#pragma unroll
    for (int i = 0; i < 8; i++) {
        int m = row0 + ty * 8 + i;
        if (m >= M) continue;
#pragma unroll
        for (int j = 0; j < 8; j++) {
            int n = col0 + tx * 8 + j;
            if (n >= N) continue;
            float r = acc[i][j];
            if (bias) r += bias[n];
            if (relu) r = fmaxf(r, 0.f);
            if (C) C[(size_t)m * ldc + n] = r;
            if (Ohi) {
                bf16 h, l;
                split_bf16(r, h, l);
                Ohi[(size_t)m * ldo + n] = h;
                Olo[(size_t)m * ldo + n] = l;
            }
        }
    }
}

// --------------------- bf16 split mma GEMM, 128xNB tiles --------------------

template <int NB>
__global__ __launch_bounds__(256, 2)
void bgemm_ep(int N, int K,
              const bf16* __restrict__ Ahi, const bf16* __restrict__ Alo, long lda,
              const bf16* __restrict__ Bhi, const bf16* __restrict__ Blo, long ldb,
              const bf16* __restrict__ Uhi, const bf16* __restrict__ Ulo,
              const bf16* __restrict__ Vhi, const bf16* __restrict__ Vlo, long ldu,
              float alpha, float beta, float gamma,
              const float* __restrict__ bias, int relu,
              bf16* __restrict__ Ohi, bf16* __restrict__ Olo, long ldo,
              float* __restrict__ Cf, long ldc) {
    constexpr int BROW = NB + 8;
    constexpr int BPL = 32 * BROW * 2;
    constexpr int STG = 20480 + 2 * BPL;
    constexpr int BSEGS = 32 * (NB / 8);       // B segs per plane
    extern __shared__ char smem[];
    const uint32_t sb = smem_u32(smem);
    const int tid = threadIdx.x, lane = tid & 31, wid = tid >> 5;
    const int wr = wid & 3, wc = wid >> 2;
    const int g = lane >> 2, t4 = lane & 3;
    const int t8 = lane & 7, quad = lane >> 3;
    const int row0 = blockIdx.y * 128, col0 = blockIdx.x * NB;
    const int NC = (K + 31) >> 5;

    float acc[2][NB / 16][4];
#pragma unroll
    for (int i = 0; i < 2; i++)
#pragma unroll
        for (int j = 0; j < NB / 16; j++)
#pragma unroll
            for (int e = 0; e < 4; e++) acc[i][j][e] = 0.f;

    auto load_stage = [&](int st, int c) {
        const long k0 = (long)c << 5;
        char* base = smem + st * STG;
#pragma unroll
        for (int q = 0; q < 2; q++) {
            int seg = tid * 2 + q;
            int row = seg >> 2, k8 = (seg & 3) << 3;
            char* da = base + 2 * (row * 40 + k8);
            if (k0 + k8 < K) {
                cpa16(smem_u32(da), Ahi + (size_t)(row0 + row) * lda + k0 + k8);
                cpa16(smem_u32(da + 10240), Alo + (size_t)(row0 + row) * lda + k0 + k8);
            } else {
                *(uint4*)da = make_uint4(0u, 0u, 0u, 0u);
                *(uint4*)(da + 10240) = make_uint4(0u, 0u, 0u, 0u);
            }
        }
#pragma unroll
        for (int q = 0; q < (BSEGS + 255) / 256; q++) {
            int seg = tid + q * 256;
            if (seg < BSEGS) {
                int row = seg / (NB / 8), n8 = (seg % (NB / 8)) << 3;
                char* db = base + 20480 + 2 * (row * BROW + n8);
                if (k0 + row < K) {
                    cpa16(smem_u32(db), Bhi + (size_t)(k0 + row) * ldb + col0 + n8);
                    cpa16(smem_u32(db + BPL), Blo + (size_t)(k0 + row) * ldb + col0 + n8);
                } else {
                    *(uint4*)db = make_uint4(0u, 0u, 0u, 0u);
                    *(uint4*)(db + BPL) = make_uint4(0u, 0u, 0u, 0u);
                }
            }
        }
    };

    load_stage(0, 0);
    CPA_COMMIT();
    if (NC > 1) load_stage(1, 1);
    CPA_COMMIT();

    const int arow = wr * 32 + ((quad & 1) << 3) + t8;
    const int acol = (quad & 2) << 2;
    const int brow = ((quad & 1) << 3) + t8;
    const int bcol = wc * (NB / 2) + ((quad & 2) << 2);

    for (int c = 0; c < NC; c++) {
        if (c < NC - 1) CPA_WAIT1(); else CPA_WAIT0();
        __syncthreads();
        const uint32_t s0 = sb + (uint32_t)((c & 1) * STG);
        const uint32_t aB = s0, bB = s0 + 20480;
#pragma unroll
        for (int kh = 0; kh < 2; kh++) {
            uint32_t ah[2][4], al[2][4];
#pragma unroll
            for (int mi = 0; mi < 2; mi++) {
                uint32_t adr = aB + 2 * ((arow + mi * 16) * 40 + acol + kh * 16);
                LDSM4(ah[mi][0], ah[mi][1], ah[mi][2], ah[mi][3], adr);
                LDSM4(al[mi][0], al[mi][1], al[mi][2], al[mi][3], adr + 10240);
            }
#pragma unroll
            for (int p = 0; p < NB / 32; p++) {
                uint32_t bh[4], bl[4];
                uint32_t bdr = bB + 2 * ((brow + kh * 16) * BROW + bcol + p * 16);
                LDSM4T(bh[0], bh[1], bh[2], bh[3], bdr);
                LDSM4T(bl[0], bl[1], bl[2], bl[3], bdr + BPL);
#pragma unroll
                for (int mi = 0; mi < 2; mi++) {
                    MMA16816(acc[mi][2 * p], ah[mi][0], ah[mi][1], ah[mi][2], ah[mi][3], bh[0], bh[1]);
                    MMA16816(acc[mi][2 * p], ah[mi][0], ah[mi][1], ah[mi][2], ah[mi][3], bl[0], bl[1]);
                    MMA16816(acc[mi][2 * p], al[mi][0], al[mi][1], al[mi][2], al[mi][3], bh[0], bh[1]);
                    MMA16816(acc[mi][2 * p + 1], ah[mi][0], ah[mi][1], ah[mi][2], ah[mi][3], bh[2], bh[3]);
                    MMA16816(acc[mi][2 * p + 1], ah[mi][0], ah[mi][1], ah[mi][2], ah[mi][3], bl[2], bl[3]);
                    MMA16816(acc[mi][2 * p + 1], al[mi][0], al[mi][1], al[mi][2], al[mi][3], bh[2], bh[3]);
                }
            }
        }
        __syncthreads();
        if (c + 2 < NC) { load_stage(c & 1, c + 2); CPA_COMMIT(); }
    }

#pragma unroll
    for (int mi = 0; mi < 2; mi++) {
        int rb = row0 + wr * 32 + mi * 16 + g;
#pragma unroll
        for (int ni = 0; ni < NB / 16; ni++) {
            int cb = col0 + wc * (NB / 2) + ni * 8 + 2 * t4;
#pragma unroll
            for (int e = 0; e < 4; e++) {
                int rr = rb + ((e >> 1) << 3);
                int cc = cb + (e & 1);
                if (cc >= N) continue;
                float r = alpha * acc[mi][ni][e];
                size_t iu = (size_t)rr * ldu + cc;
                if (Uhi) r += beta * (__bfloat162float(Uhi[iu]) + __bfloat162float(Ulo[iu]));
                if (Vhi) r += gamma * (__bfloat162float(Vhi[iu]) + __bfloat162float(Vlo[iu]));
                if (bias) r += bias[cc];
                if (relu) r = fmaxf(r, 0.f);
                if (Cf) Cf[(size_t)rr * ldc + cc] = r;
                if (Ohi) {
                    bf16 h, l;
                    split_bf16(r, h, l);
                    Ohi[(size_t)rr * ldo + cc] = h;
                    Olo[(size_t)rr * ldo + cc] = l;
                }
            }
        }
    }
}

// ------------------------------- host side ----------------------------------

#define STG128 37888
#define STG64  29696
#define STG32  25600

static void set_attrs_once() {
    static int done = 0;
    if (!done) {
        cudaFuncSetAttribute(bgemm_ep<128>, cudaFuncAttributeMaxDynamicSharedMemorySize, 2 * STG128);
        cudaFuncSetAttribute(bgemm_ep<64>, cudaFuncAttributeMaxDynamicSharedMemorySize, 2 * STG64);
        cudaFuncSetAttribute(bgemm_ep<32>, cudaFuncAttributeMaxDynamicSharedMemorySize, 2 * STG32);
        done = 1;
    }
}

static inline void bgemm_launch(int N, int K,
                                const bf16* Ahi, const bf16* Alo, long lda,
                                const bf16* Bhi, const bf16* Blo, long ldb,
                                const bf16* Uhi, const bf16* Ulo,
                                const bf16* Vhi, const bf16* Vlo, long ldu,
                                float al, float be, float ga,
                                const float* bias, int relu,
                                bf16* Ohi, bf16* Olo, long ldo,
                                float* Cf, long ldc) {
    set_attrs_once();
    if (N <= 280) {
        dim3 grid((N + 31) / 32, 32);
        bgemm_ep<32><<<grid, 256, 2 * STG32>>>(N, K, Ahi, Alo, lda, Bhi, Blo, ldb,
                                               Uhi, Ulo, Vhi, Vlo, ldu, al, be, ga,
                                               bias, relu, Ohi, Olo, ldo, Cf, ldc);
    } else if (N <= 560) {
        dim3 grid((N + 63) / 64, 32);
        bgemm_ep<64><<<grid, 256, 2 * STG64>>>(N, K, Ahi, Alo, lda, Bhi, Blo, ldb,
                                               Uhi, Ulo, Vhi, Vlo, ldu, al, be, ga,
                                               bias, relu, Ohi, Olo, ldo, Cf, ldc);
    } else {
        dim3 grid((N + 127) / 128, 32);
        bgemm_ep<128><<<grid, 256, 2 * STG128>>>(N, K, Ahi, Alo, lda, Bhi, Blo, ldb,
                                                 Uhi, Ulo, Vhi, Vlo, ldu, al, be, ga,
                                                 bias, relu, Ohi, Olo, ldo, Cf, ldc);
    }
}

extern "C" void kernel_launch(void* const* d_in, const int* in_sizes, int n_in,
                              void* d_out, int out_size) {
    const float* x     = (const float*)d_in[0];
    const float* adj   = (const float*)d_in[1];
    const float* W1    = (const float*)d_in[2];
    const float* b1    = (const float*)d_in[3];
    const float* W2    = (const float*)d_in[4];
    const float* b2    = (const float*)d_in[5];
    const float* W3    = (const float*)d_in[6];
    const float* b3    = (const float*)d_in[7];
    const float* W4    = (const float*)d_in[8];
    const float* b4    = (const float*)d_in[9];
    const float* fc1_w = (const float*)d_in[10];
    const float* fc1_b = (const float*)d_in[11];
    const float* fc2_w = (const float*)d_in[12];
    const float* fc2_b = (const float*)d_in[13];
    float* out = (float*)d_out;

    void* p;
    float *dinv, *Tw1, *H4, *Hfc;
    bf16 *Ashi, *Aslo, *TAhi, *TAlo, *TBhi, *TBlo;
    bf16 *W2hi, *W2lo, *W3hi, *W3lo, *W4hi, *W4lo;
    cudaGetSymbolAddress(&p, g_AsHi); Ashi = (bf16*)p;
    cudaGetSymbolAddress(&p, g_AsLo); Aslo = (bf16*)p;
    cudaGetSymbolAddress(&p, g_dinv); dinv = (float*)p;
    cudaGetSymbolAddress(&p, g_Tw1);  Tw1  = (float*)p;
    cudaGetSymbolAddress(&p, g_TAhi); TAhi = (bf16*)p;
    cudaGetSymbolAddress(&p, g_TAlo); TAlo = (bf16*)p;
    cudaGetSymbolAddress(&p, g_TBhi); TBhi = (bf16*)p;
    cudaGetSymbolAddress(&p, g_TBlo); TBlo = (bf16*)p;
    cudaGetSymbolAddress(&p, g_W2hi); W2hi = (bf16*)p;
    cudaGetSymbolAddress(&p, g_W2lo); W2lo = (bf16*)p;
    cudaGetSymbolAddress(&p, g_W3hi); W3hi = (bf16*)p;
    cudaGetSymbolAddress(&p, g_W3lo); W3lo = (bf16*)p;
    cudaGetSymbolAddress(&p, g_W4hi); W4hi = (bf16*)p;
    cudaGetSymbolAddress(&p, g_W4lo); W4lo = (bf16*)p;
    cudaGetSymbolAddress(&p, g_H4);   H4   = (float*)p;
    cudaGetSymbolAddress(&p, g_Hfc);  Hfc  = (float*)p;

    // ---- preprocess ----
    deg_kernel<<<NN, 256>>>(adj, dinv);
    scale_adj_split<<<NN, 256>>>(adj, dinv, Ashi, Aslo);
    split_kernel<<<2048, 256>>>(W2, W2hi, W2lo, 5 * 1120 * 560);
    split_kernel<<<1024, 256>>>(W3, W3hi, W3lo, 4 * 560 * 280);
    split_pad_kernel<<<256, 256>>>(W4, W4hi, W4lo, 3 * 280, 140, 144);

    // ---- layer 1 (cin=7, k=6): skinny path on As planes ----
    copy_x_kernel<<<(NN * 7 + 255) / 256, 256>>>(x, Tw1);
    for (int i = 1; i < 6; i++) {
        float al = (i == 1) ? -1.f : -2.f, be = (i == 1) ? 1.f : 2.f;
        gemm_skinny_pk<<<NN, 256>>>(7, NN, Ashi, Aslo, NN, Tw1 + (i - 1) * 7, 42,
                                    Tw1 + i * 7, 42, Tw1 + (i - 1) * 7,
                                    (i >= 2) ? Tw1 + (i - 2) * 7 : nullptr,
                                    al, be, -1.f);
    }
    {
        dim3 g((1120 + 127) / 128, 32);
        sgemm_ep<<<g, 256>>>(NN, 1120, 42, Tw1, 42, W1, 1120,
                             nullptr, 0, b1, 1, TAhi, TAlo, 5600);
    }

    // ---- layers 2..4 : bf16 split mma path ----
    struct Cfg {
        int cin, cout, k, ldi, ldw, ldnext;
        bf16 *inhi, *inlo, *outhi, *outlo, *whi, *wlo;
        const float* bias;
    };
    Cfg L[3] = {
        {1120, 560, 5, 5600, 560, 2240, TAhi, TAlo, TBhi, TBlo, W2hi, W2lo, b2},
        {560, 280, 4, 2240, 280, 840, TBhi, TBlo, TAhi, TAlo, W3hi, W3lo, b3},
        {280, 140, 3, 840, 144, 0, TAhi, TAlo, nullptr, nullptr, W4hi, W4lo, b4},
    };
    for (int l = 0; l < 3; l++) {
        Cfg& c = L[l];
        for (int i = 1; i < c.k; i++) {
            float al = (i == 1) ? -1.f : -2.f, be = (i == 1) ? 1.f : 2.f;
            const bf16* Uh = c.inhi + (size_t)(i - 1) * c.cin;
            const bf16* Ul = c.inlo + (size_t)(i - 1) * c.cin;
            const bf16* Vh = (i >= 2) ? c.inhi + (size_t)(i - 2) * c.cin : nullptr;
            const bf16* Vl = (i >= 2) ? c.inlo + (size_t)(i - 2) * c.cin : nullptr;
            bgemm_launch(c.cin, NN, Ashi, Aslo, NN, Uh, Ul, c.ldi,
                         Uh, Ul, Vh, Vl, c.ldi, al, be, -1.f, nullptr, 0,
                         c.inhi + (size_t)i * c.cin, c.inlo + (size_t)i * c.cin,
                         c.ldi, nullptr, 0);
        }
        int K = c.k * c.cin;
        if (l < 2) {
            bgemm_launch(c.cout, K, c.inhi, c.inlo, c.ldi, c.whi, c.wlo, c.ldw,
                         nullptr, nullptr, nullptr, nullptr, c.ldnext,
                         1.f, 0.f, 0.f, c.bias, 1,
                         c.outhi, c.outlo, c.ldnext, nullptr, 0);
        } else {
            bgemm_launch(c.cout, K, c.inhi, c.inlo, c.ldi, c.whi, c.wlo, c.ldw,
                         nullptr, nullptr, nullptr, nullptr, 140,
                         1.f, 0.f, 0.f, c.bias, 1,
                         nullptr, nullptr, 0, H4, 140);
        }
    }

    // ---- FC layers (fp32) ----
    {
        dim3 g((140 + 127) / 128, 32);
        sgemm_ep<<<g, 256>>>(NN, 140, 140, H4, 140, fc1_w, 140, Hfc, 140,
                             fc1_b, 0, nullptr, nullptr, 0);
    }
    gemm_skinny<<<NN, 256>>>(4, 140, Hfc, 140, fc2_w, 4, out, 4, fc2_b);
}